// round 15
// baseline (speedup 1.0000x reference)
#include <cuda_runtime.h>
#include <math.h>

// Problem shape (fixed by dataset): N=100000, H=32, K=15, C_in=C_out=64
#define MAXN 100000
#define NB_H 32
#define KPTS 15
#define CH   64

#define NBLOCKS       148                // 1 block per SM (100KB smem each)
#define NTHREADS      512
#define NWARPS        16
#define TOTAL_THREADS (NBLOCKS * NTHREADS)
#define TOTAL_WARPS   (NBLOCKS * NWARPS)

#define SLICE_CAP     25600              // uint codes per smem slice (100 KB)
#define SMEM_BYTES    (SLICE_CAP * 4)

// quantization of s_pts into one uint32: 10 bits per coord over [QLO, QLO+QRANGE]
#define QLO     (-6.5f)
#define QRANGE  (13.0f)
#define QSCALE  (1023.0f / QRANGE)
#define QINV    (QRANGE / 1023.0f)
#define QERR3D  (0.0115f)                // > sqrt(3)/2 * QINV = 0.01101

// Scratch (__device__ globals: allocation-free rule)
__device__ unsigned g_code[MAXN];    // quantized s_pts (bit30 = force-hit / out-of-range)
__device__ float  g_val[MAXN * CH];  // raw kpconv rows for flagged points
__device__ int    g_flag[MAXN];      // 1 if candidate row
__device__ float  g_sum[CH];
__device__ float  g_sumsq[CH];
// software grid barrier (self-resetting, safe across graph replays)
__device__ int          g_bar_count = 0;
__device__ volatile int g_bar_gen   = 0;

static __host__ __device__ __forceinline__ float kp_extent() {
    return (float)(0.1 * 1.2 / 2.5);
}

static __device__ __forceinline__ void grid_sync() {
    __threadfence();
    __syncthreads();
    if (threadIdx.x == 0) {
        const int gen = g_bar_gen;
        if (atomicAdd(&g_bar_count, 1) == NBLOCKS - 1) {
            g_bar_count = 0;
            __threadfence();
            g_bar_gen = gen + 1;
        } else {
            while (g_bar_gen == gen) { __nanosleep(32); }
        }
    }
    __syncthreads();
}

static __device__ __forceinline__ unsigned pack_code(float x, float y, float z) {
    const float fx = (x - QLO) * QSCALE;
    const float fy = (y - QLO) * QSCALE;
    const float fz = (z - QLO) * QSCALE;
    if (fx < 0.0f || fx > 1023.0f || fy < 0.0f || fy > 1023.0f ||
        fz < 0.0f || fz > 1023.0f)
        return 0x40000000u;              // conservative force-hit
    const unsigned cx = (unsigned)__float2int_rn(fx);
    const unsigned cy = (unsigned)__float2int_rn(fy);
    const unsigned cz = (unsigned)__float2int_rn(fz);
    return cx | (cy << 10) | (cz << 20);
}

static __device__ __forceinline__ bool code_hit(unsigned c, float qx, float qy, float qz,
                                                float thr2) {
    if (c & 0x40000000u) return true;
    const float sx = fmaf((float)(c & 1023u),         QINV, QLO);
    const float sy = fmaf((float)((c >> 10) & 1023u), QINV, QLO);
    const float sz = fmaf((float)((c >> 20) & 1023u), QINV, QLO);
    const float dx = sx - qx, dy = sy - qy, dz = sz - qz;
    return fmaf(dx, dx, fmaf(dy, dy, dz * dz)) < thr2;
}

__global__ void __launch_bounds__(NTHREADS, 1) fused_kernel(
    const float* __restrict__ q_pts,
    const float* __restrict__ s_pts,
    const int*   __restrict__ inds,
    const float* __restrict__ x,
    const float* __restrict__ kp,
    const float* __restrict__ W,    // [K, C, C]
    float* __restrict__ out, int N)
{
    extern __shared__ unsigned sm_dyn[];     // 100 KB: slice codes / heavy staging (reused)
    __shared__ float mm[CH], iv[CH], zz[CH];

    const int tid   = threadIdx.x;
    const int warp  = tid >> 5;
    const int lane  = tid & 31;
    const int gtid  = blockIdx.x * NTHREADS + tid;
    const int gwarp = blockIdx.x * NWARPS + warp;
    const unsigned FULL = 0xffffffffu;

    // conservative candidate threshold^2 (+QERR3D covers quantization of s)
    float thr2;
    {
        float mx2 = 0.0f;
#pragma unroll
        for (int k = 0; k < KPTS; k++) {
            const float a = __ldg(kp + 3*k), b = __ldg(kp + 3*k + 1), c = __ldg(kp + 3*k + 2);
            mx2 = fmaxf(mx2, fmaf(a, a, fmaf(b, b, c * c)));
        }
        const float t = (kp_extent() + sqrtf(mx2)) * 1.0002f + QERR3D;  // false positives ok
        thr2 = t * t;
    }

    // ---------------- Phase A: quantize s_pts -> codes (vectorized), zero flags/sums ----------------
    {
        const float4* __restrict__ s4 = reinterpret_cast<const float4*>(s_pts);
        const int nq = N >> 2;
        for (int i = gtid; i < nq; i += TOTAL_THREADS) {
            const float4 a = __ldg(s4 + (long)i * 3);
            const float4 b = __ldg(s4 + (long)i * 3 + 1);
            const float4 c = __ldg(s4 + (long)i * 3 + 2);
            const int p = i << 2;
            uint4 codes;
            codes.x = pack_code(a.x, a.y, a.z);
            codes.y = pack_code(a.w, b.x, b.y);
            codes.z = pack_code(b.z, b.w, c.x);
            codes.w = pack_code(c.y, c.z, c.w);
            *reinterpret_cast<uint4*>(&g_code[p]) = codes;
            *reinterpret_cast<int4*>(&g_flag[p]) = make_int4(0, 0, 0, 0);
        }
        for (int i = (nq << 2) + gtid; i < N; i += TOTAL_THREADS) {   // generic tail
            g_flag[i] = 0;
            g_code[i] = pack_code(__ldg(s_pts + 3*i), __ldg(s_pts + 3*i + 1),
                                  __ldg(s_pts + 3*i + 2));
        }
        if (blockIdx.x == 0 && tid < CH) { g_sum[tid] = 0.0f; g_sumsq[tid] = 0.0f; }
    }
    grid_sync();

    // ------- Phase B: detect via SMEM slice scan (no L1tex gathers) -------
    {
        const int nquad = N * (NB_H / 4);        // 800000 int4 quads
        const int slice = (N + 3) >> 2;          // <= SLICE_CAP for N <= 102400
        for (int s = 0; s < 4; s++) {
            const int lo  = s * slice;
            const int cnt = min(slice, N - lo);
            if (cnt <= 0) break;

            // stage slice codes into smem (coalesced)
            for (int i = tid; i < cnt; i += NTHREADS)
                sm_dyn[i] = g_code[lo + i];
            __syncthreads();

            for (int t = gtid; t < nquad; t += TOTAL_THREADS) {
                const int n = t >> 3;            // 8 quads per point
                const int4 iv4 = __ldg(reinterpret_cast<const int4*>(inds) + t);

                // quick range screen: skip q loads if no id in slice
                const unsigned r0 = (unsigned)(iv4.x - lo);
                const unsigned r1 = (unsigned)(iv4.y - lo);
                const unsigned r2i = (unsigned)(iv4.z - lo);
                const unsigned r3 = (unsigned)(iv4.w - lo);
                const unsigned ucnt = (unsigned)cnt;
                if (r0 >= ucnt && r1 >= ucnt && r2i >= ucnt && r3 >= ucnt) continue;

                const float qx = __ldg(q_pts + 3*n);
                const float qy = __ldg(q_pts + 3*n + 1);
                const float qz = __ldg(q_pts + 3*n + 2);

                bool any = false;
                if (r0  < ucnt) any |= code_hit(sm_dyn[r0],  qx, qy, qz, thr2);
                if (r1  < ucnt) any |= code_hit(sm_dyn[r1],  qx, qy, qz, thr2);
                if (r2i < ucnt) any |= code_hit(sm_dyn[r2i], qx, qy, qz, thr2);
                if (r3  < ucnt) any |= code_hit(sm_dyn[r3],  qx, qy, qz, thr2);
                if (any) g_flag[n] = 1;          // racy same-value store: benign
            }
            __syncthreads();                     // all reads done before next slice overwrites
        }
    }
    grid_sync();

    // ---------------- Phase B2: heavy. ballot-scan flags, exact KPConv per hit ----------------
    // Exact path uses the ORIGINAL fp32 s_pts. sw staging reuses the slice smem.
    {
        float (*sw)[KPTS][CH] = reinterpret_cast<float (*)[KPTS][CH]>(sm_dyn);  // 16*15*64*4 = 61440 B

        const float EXT  = kp_extent();
        const float EXT2 = EXT * EXT;
        const float INVE = 1.0f / EXT;

        const int ngrp = (N + 31) >> 5;
        for (int g = gwarp; g < ngrp; g += TOTAL_WARPS) {
            const int fn = g * 32 + lane;
            const int f = (fn < N) ? g_flag[fn] : 0;
            unsigned hits = __ballot_sync(FULL, f != 0);

            while (hits) {
                const int bit = __ffs(hits) - 1;
                hits &= (hits - 1);
                const int n = g * 32 + bit;

                const float qx = __ldg(q_pts + 3*n);
                const float qy = __ldg(q_pts + 3*n + 1);
                const float qz = __ldg(q_pts + 3*n + 2);

                const int idx = __ldg(inds + (long)n * NB_H + lane);
                const bool valid = ((unsigned)idx < (unsigned)N);
                float nx = 1e9f, ny = 1e9f, nz = 1e9f;
                if (valid) {
                    nx = __ldg(s_pts + 3*idx)     - qx;
                    ny = __ldg(s_pts + 3*idx + 1) - qy;
                    nz = __ldg(s_pts + 3*idx + 2) - qz;
                }
                const float r2 = fmaf(nx, nx, fmaf(ny, ny, nz * nz));
                unsigned mask = __ballot_sync(FULL, valid && (r2 < thr2));

                float acc0[KPTS], acc1[KPTS];
#pragma unroll
                for (int k = 0; k < KPTS; k++) { acc0[k] = 0.0f; acc1[k] = 0.0f; }

                unsigned m = mask;
                while (m) {
                    const int hs = __ffs(m) - 1;
                    m &= (m - 1);
                    const int   sidx = __shfl_sync(FULL, idx, hs);
                    const float bx = __shfl_sync(FULL, nx, hs);
                    const float by = __shfl_sync(FULL, ny, hs);
                    const float bz = __shfl_sync(FULL, nz, hs);
                    const float xv0 = __ldg(x + (long)sidx * CH + lane);
                    const float xv1 = __ldg(x + (long)sidx * CH + lane + 32);
#pragma unroll
                    for (int k = 0; k < KPTS; k++) {
                        const float dx = bx - __ldg(kp + 3*k);
                        const float dy = by - __ldg(kp + 3*k + 1);
                        const float dz = bz - __ldg(kp + 3*k + 2);
                        const float d2 = fmaf(dx, dx, fmaf(dy, dy, dz * dz));
                        if (d2 < EXT2) {
                            const float w = fmaxf(1.0f - sqrtf(d2) * INVE, 0.0f);
                            acc0[k] = fmaf(w, xv0, acc0[k]);
                            acc1[k] = fmaf(w, xv1, acc1[k]);
                        }
                    }
                }

                unsigned kmask = 0;
#pragma unroll
                for (int k = 0; k < KPTS; k++) {
                    sw[warp][k][lane]      = acc0[k];
                    sw[warp][k][lane + 32] = acc1[k];
                    if (__ballot_sync(FULL, (acc0[k] != 0.0f) || (acc1[k] != 0.0f)))
                        kmask |= (1u << k);
                }
                __syncwarp();

                float o0 = 0.0f, o1 = 0.0f;
                for (int k = 0; k < KPTS; k++) {
                    if (!(kmask & (1u << k))) continue;
                    const float* Wk = W + (long)k * CH * CH;
#pragma unroll 8
                    for (int c = 0; c < CH; c++) {
                        const float wv = sw[warp][k][c];
                        o0 = fmaf(wv, __ldg(Wk + c * CH + lane),      o0);
                        o1 = fmaf(wv, __ldg(Wk + c * CH + lane + 32), o1);
                    }
                }
                __syncwarp();

                g_val[(long)n * CH + lane]      = o0;
                g_val[(long)n * CH + lane + 32] = o1;
                atomicAdd(&g_sum[lane],        o0);
                atomicAdd(&g_sum[lane + 32],   o1);
                atomicAdd(&g_sumsq[lane],      o0 * o0);
                atomicAdd(&g_sumsq[lane + 32], o1 * o1);
            }
        }
    }
    grid_sync();

    // ---------------- Phase C: finalize stats, stream output ----------------
    if (tid < CH) {
        const float invN = 1.0f / (float)N;
        const float mean = g_sum[tid] * invN;
        const float var  = fmaxf(g_sumsq[tid] * invN - mean * mean, 0.0f);
        const float inv  = rsqrtf(var + 1e-5f);
        const float z    = (0.0f - mean) * inv;
        mm[tid] = mean;
        iv[tid] = inv;
        zz[tid] = (z >= 0.0f) ? z : 0.1f * z;
    }
    __syncthreads();

    {
        float4* __restrict__ out4 = reinterpret_cast<float4*>(out);
        const int c4 = (lane & 15) * 4;
        const float4 vz = make_float4(zz[c4], zz[c4 + 1], zz[c4 + 2], zz[c4 + 3]);
        const int ngrp = (N + 31) >> 5;   // 32-row groups

        for (int g = gwarp; g < ngrp; g += TOTAL_WARPS) {
            const int r0 = g * 32;
            const int fn = r0 + lane;
            const int f  = (fn < N) ? g_flag[fn] : 0;   // one coalesced load per warp
            const unsigned hits = __ballot_sync(FULL, f != 0);

            if (hits == 0 && r0 + 32 <= N) {
                const long base = (long)g * 512;        // float4 units (32 rows * 16)
#pragma unroll
                for (int j = 0; j < 16; j++)
                    out4[base + j * 32 + lane] = vz;
            } else {
                const int rend = min(r0 + 32, N);
                for (int r = r0; r < rend; r++) {
                    const int fr = __shfl_sync(FULL, f, r - r0);
                    float a0, a1;
                    if (fr) {
                        const float v0 = g_val[(long)r * CH + lane];
                        const float v1 = g_val[(long)r * CH + lane + 32];
                        a0 = (v0 - mm[lane])      * iv[lane];
                        a1 = (v1 - mm[lane + 32]) * iv[lane + 32];
                        a0 = (a0 >= 0.0f) ? a0 : 0.1f * a0;
                        a1 = (a1 >= 0.0f) ? a1 : 0.1f * a1;
                    } else {
                        a0 = zz[lane];
                        a1 = zz[lane + 32];
                    }
                    out[(long)r * CH + lane]      = a0;
                    out[(long)r * CH + lane + 32] = a1;
                }
            }
        }
    }
}

// ---------------- launch: ONE kernel ----------------
extern "C" void kernel_launch(void* const* d_in, const int* in_sizes, int n_in,
                              void* d_out, int out_size) {
    const float* q_pts = (const float*)d_in[0];
    const float* s_pts = (const float*)d_in[1];
    const int*   inds  = (const int*)  d_in[2];
    const float* x     = (const float*)d_in[3];
    const float* kp    = (const float*)d_in[4];
    const float* W     = (const float*)d_in[5];
    float* out = (float*)d_out;

    const int N = in_sizes[0] / 3;

    // non-stream attribute call: capture-safe, idempotent, no allocation
    cudaFuncSetAttribute(fused_kernel, cudaFuncAttributeMaxDynamicSharedMemorySize,
                         SMEM_BYTES);
    fused_kernel<<<NBLOCKS, NTHREADS, SMEM_BYTES>>>(q_pts, s_pts, inds, x, kp, W, out, N);
}

// round 16
// speedup vs baseline: 1.4505x; 1.4505x over previous
#include <cuda_runtime.h>
#include <math.h>

// Problem shape (fixed by dataset): N=100000, H=32, K=15, C_in=C_out=64
#define MAXN 100000
#define NB_H 32
#define KPTS 15
#define CH   64

#define NBLOCKS       148                // 1 block per SM (100KB dynamic smem)
#define NTHREADS      512
#define NWARPS        16
#define TOTAL_THREADS (NBLOCKS * NTHREADS)
#define TOTAL_WARPS   (NBLOCKS * NWARPS)

#define SLICE         25600              // ids < SLICE resolved via smem (100 KB)
#define SMEM_BYTES    (SLICE * 4)

// quantization of s_pts into one uint32: 10 bits per coord over [QLO, QLO+QRANGE]
#define QLO     (-6.5f)
#define QRANGE  (13.0f)
#define QSCALE  (1023.0f / QRANGE)
#define QINV    (QRANGE / 1023.0f)
#define QERR3D  (0.0115f)                // > sqrt(3)/2 * QINV = 0.01101

// Scratch (__device__ globals: allocation-free rule)
__device__ unsigned g_code[MAXN];    // quantized s_pts (bit30 = force-hit / out-of-range)
__device__ float  g_val[MAXN * CH];  // raw kpconv rows for flagged points
__device__ int    g_flag[MAXN];      // 1 if candidate row
__device__ float  g_sum[CH];
__device__ float  g_sumsq[CH];
// software grid barrier (self-resetting, safe across graph replays)
__device__ int          g_bar_count = 0;
__device__ volatile int g_bar_gen   = 0;

static __host__ __device__ __forceinline__ float kp_extent() {
    return (float)(0.1 * 1.2 / 2.5);
}

static __device__ __forceinline__ void grid_sync() {
    __threadfence();
    __syncthreads();
    if (threadIdx.x == 0) {
        const int gen = g_bar_gen;
        if (atomicAdd(&g_bar_count, 1) == NBLOCKS - 1) {
            g_bar_count = 0;
            __threadfence();
            g_bar_gen = gen + 1;
        } else {
            while (g_bar_gen == gen) { __nanosleep(32); }
        }
    }
    __syncthreads();
}

static __device__ __forceinline__ unsigned pack_code(float x, float y, float z) {
    const float fx = (x - QLO) * QSCALE;
    const float fy = (y - QLO) * QSCALE;
    const float fz = (z - QLO) * QSCALE;
    if (fx < 0.0f || fx > 1023.0f || fy < 0.0f || fy > 1023.0f ||
        fz < 0.0f || fz > 1023.0f)
        return 0x40000000u;              // conservative force-hit
    const unsigned cx = (unsigned)__float2int_rn(fx);
    const unsigned cy = (unsigned)__float2int_rn(fy);
    const unsigned cz = (unsigned)__float2int_rn(fz);
    return cx | (cy << 10) | (cz << 20);
}

static __device__ __forceinline__ bool code_hit(unsigned c, float qx, float qy, float qz,
                                                float thr2) {
    const float sx = fmaf((float)(c & 1023u),         QINV, QLO);
    const float sy = fmaf((float)((c >> 10) & 1023u), QINV, QLO);
    const float sz = fmaf((float)((c >> 20) & 1023u), QINV, QLO);
    const float dx = sx - qx, dy = sy - qy, dz = sz - qz;
    return (fmaf(dx, dx, fmaf(dy, dy, dz * dz)) < thr2) | ((c & 0x40000000u) != 0u);
}

__global__ void __launch_bounds__(NTHREADS, 1) fused_kernel(
    const float* __restrict__ q_pts,
    const float* __restrict__ s_pts,
    const int*   __restrict__ inds,
    const float* __restrict__ x,
    const float* __restrict__ kp,
    const float* __restrict__ W,    // [K, C, C]
    float* __restrict__ out, int N)
{
    extern __shared__ unsigned sm_dyn[];     // 100 KB: code slice / heavy staging (reused)
    __shared__ float mm[CH], iv[CH], zz[CH];

    const int tid   = threadIdx.x;
    const int warp  = tid >> 5;
    const int lane  = tid & 31;
    const int gtid  = blockIdx.x * NTHREADS + tid;
    const int gwarp = blockIdx.x * NWARPS + warp;
    const unsigned FULL = 0xffffffffu;

    // conservative candidate threshold^2 (+QERR3D covers quantization of s)
    float thr2;
    {
        float mx2 = 0.0f;
#pragma unroll
        for (int k = 0; k < KPTS; k++) {
            const float a = __ldg(kp + 3*k), b = __ldg(kp + 3*k + 1), c = __ldg(kp + 3*k + 2);
            mx2 = fmaxf(mx2, fmaf(a, a, fmaf(b, b, c * c)));
        }
        const float t = (kp_extent() + sqrtf(mx2)) * 1.0002f + QERR3D;  // false positives ok
        thr2 = t * t;
    }

    // ---------------- Phase A: quantize s_pts -> codes (vectorized), zero flags/sums ----------------
    {
        const float4* __restrict__ s4 = reinterpret_cast<const float4*>(s_pts);
        const int nq = N >> 2;
        for (int i = gtid; i < nq; i += TOTAL_THREADS) {
            const float4 a = __ldg(s4 + (long)i * 3);
            const float4 b = __ldg(s4 + (long)i * 3 + 1);
            const float4 c = __ldg(s4 + (long)i * 3 + 2);
            const int p = i << 2;
            uint4 codes;
            codes.x = pack_code(a.x, a.y, a.z);
            codes.y = pack_code(a.w, b.x, b.y);
            codes.z = pack_code(b.z, b.w, c.x);
            codes.w = pack_code(c.y, c.z, c.w);
            *reinterpret_cast<uint4*>(&g_code[p]) = codes;
            *reinterpret_cast<int4*>(&g_flag[p]) = make_int4(0, 0, 0, 0);
        }
        for (int i = (nq << 2) + gtid; i < N; i += TOTAL_THREADS) {   // generic tail
            g_flag[i] = 0;
            g_code[i] = pack_code(__ldg(s_pts + 3*i), __ldg(s_pts + 3*i + 1),
                                  __ldg(s_pts + 3*i + 2));
        }
        if (blockIdx.x == 0 && tid < CH) { g_sum[tid] = 0.0f; g_sumsq[tid] = 0.0f; }
    }
    grid_sync();

    // ------- Phase B: detect, SINGLE pass. ids < SLICE via smem LDS, rest via LDG -------
    {
        // stage the fixed slice once (coalesced; g_code[0..SLICE) complete after grid_sync)
        const int scnt = min(SLICE, N);
        for (int i = tid; i < scnt; i += NTHREADS)
            sm_dyn[i] = g_code[i];
        __syncthreads();

        const int nquad = N * (NB_H / 4);   // 800000 int4 quads
        for (int t = gtid; t < nquad; t += TOTAL_THREADS) {
            const int n = t >> 3;           // 8 quads per point; q loads broadcast in-warp
            const float qx = __ldg(q_pts + 3*n);
            const float qy = __ldg(q_pts + 3*n + 1);
            const float qz = __ldg(q_pts + 3*n + 2);

            const int4 iv4 = __ldg(reinterpret_cast<const int4*>(inds) + t);

            // dataset guarantees idx in [0, N)
            const unsigned c0 = (iv4.x < SLICE) ? sm_dyn[iv4.x] : __ldg(&g_code[iv4.x]);
            const unsigned c1 = (iv4.y < SLICE) ? sm_dyn[iv4.y] : __ldg(&g_code[iv4.y]);
            const unsigned c2 = (iv4.z < SLICE) ? sm_dyn[iv4.z] : __ldg(&g_code[iv4.z]);
            const unsigned c3 = (iv4.w < SLICE) ? sm_dyn[iv4.w] : __ldg(&g_code[iv4.w]);

            bool any = false;
            any |= code_hit(c0, qx, qy, qz, thr2);
            any |= code_hit(c1, qx, qy, qz, thr2);
            any |= code_hit(c2, qx, qy, qz, thr2);
            any |= code_hit(c3, qx, qy, qz, thr2);

            if (any) g_flag[n] = 1;         // racy same-value store: benign
        }
    }
    grid_sync();

    // ---------------- Phase B2: heavy. ballot-scan flags, exact KPConv per hit ----------------
    // Exact path uses the ORIGINAL fp32 s_pts. sw staging reuses the slice smem.
    {
        float (*sw)[KPTS][CH] = reinterpret_cast<float (*)[KPTS][CH]>(sm_dyn);  // 61440 B

        const float EXT  = kp_extent();
        const float EXT2 = EXT * EXT;
        const float INVE = 1.0f / EXT;

        const int ngrp = (N + 31) >> 5;
        for (int g = gwarp; g < ngrp; g += TOTAL_WARPS) {
            const int fn = g * 32 + lane;
            const int f = (fn < N) ? g_flag[fn] : 0;
            unsigned hits = __ballot_sync(FULL, f != 0);

            while (hits) {
                const int bit = __ffs(hits) - 1;
                hits &= (hits - 1);
                const int n = g * 32 + bit;

                const float qx = __ldg(q_pts + 3*n);
                const float qy = __ldg(q_pts + 3*n + 1);
                const float qz = __ldg(q_pts + 3*n + 2);

                const int idx = __ldg(inds + (long)n * NB_H + lane);
                const bool valid = ((unsigned)idx < (unsigned)N);
                float nx = 1e9f, ny = 1e9f, nz = 1e9f;
                if (valid) {
                    nx = __ldg(s_pts + 3*idx)     - qx;
                    ny = __ldg(s_pts + 3*idx + 1) - qy;
                    nz = __ldg(s_pts + 3*idx + 2) - qz;
                }
                const float r2 = fmaf(nx, nx, fmaf(ny, ny, nz * nz));
                unsigned mask = __ballot_sync(FULL, valid && (r2 < thr2));

                float acc0[KPTS], acc1[KPTS];
#pragma unroll
                for (int k = 0; k < KPTS; k++) { acc0[k] = 0.0f; acc1[k] = 0.0f; }

                unsigned m = mask;
                while (m) {
                    const int hs = __ffs(m) - 1;
                    m &= (m - 1);
                    const int   sidx = __shfl_sync(FULL, idx, hs);
                    const float bx = __shfl_sync(FULL, nx, hs);
                    const float by = __shfl_sync(FULL, ny, hs);
                    const float bz = __shfl_sync(FULL, nz, hs);
                    const float xv0 = __ldg(x + (long)sidx * CH + lane);
                    const float xv1 = __ldg(x + (long)sidx * CH + lane + 32);
#pragma unroll
                    for (int k = 0; k < KPTS; k++) {
                        const float dx = bx - __ldg(kp + 3*k);
                        const float dy = by - __ldg(kp + 3*k + 1);
                        const float dz = bz - __ldg(kp + 3*k + 2);
                        const float d2 = fmaf(dx, dx, fmaf(dy, dy, dz * dz));
                        if (d2 < EXT2) {
                            const float w = fmaxf(1.0f - sqrtf(d2) * INVE, 0.0f);
                            acc0[k] = fmaf(w, xv0, acc0[k]);
                            acc1[k] = fmaf(w, xv1, acc1[k]);
                        }
                    }
                }

                unsigned kmask = 0;
#pragma unroll
                for (int k = 0; k < KPTS; k++) {
                    sw[warp][k][lane]      = acc0[k];
                    sw[warp][k][lane + 32] = acc1[k];
                    if (__ballot_sync(FULL, (acc0[k] != 0.0f) || (acc1[k] != 0.0f)))
                        kmask |= (1u << k);
                }
                __syncwarp();

                float o0 = 0.0f, o1 = 0.0f;
                for (int k = 0; k < KPTS; k++) {
                    if (!(kmask & (1u << k))) continue;
                    const float* Wk = W + (long)k * CH * CH;
#pragma unroll 8
                    for (int c = 0; c < CH; c++) {
                        const float wv = sw[warp][k][c];
                        o0 = fmaf(wv, __ldg(Wk + c * CH + lane),      o0);
                        o1 = fmaf(wv, __ldg(Wk + c * CH + lane + 32), o1);
                    }
                }
                __syncwarp();

                g_val[(long)n * CH + lane]      = o0;
                g_val[(long)n * CH + lane + 32] = o1;
                atomicAdd(&g_sum[lane],        o0);
                atomicAdd(&g_sum[lane + 32],   o1);
                atomicAdd(&g_sumsq[lane],      o0 * o0);
                atomicAdd(&g_sumsq[lane + 32], o1 * o1);
            }
        }
    }
    grid_sync();

    // ---------------- Phase C: finalize stats, stream output ----------------
    if (tid < CH) {
        const float invN = 1.0f / (float)N;
        const float mean = g_sum[tid] * invN;
        const float var  = fmaxf(g_sumsq[tid] * invN - mean * mean, 0.0f);
        const float inv  = rsqrtf(var + 1e-5f);
        const float z    = (0.0f - mean) * inv;
        mm[tid] = mean;
        iv[tid] = inv;
        zz[tid] = (z >= 0.0f) ? z : 0.1f * z;
    }
    __syncthreads();

    {
        float4* __restrict__ out4 = reinterpret_cast<float4*>(out);
        const int c4 = (lane & 15) * 4;
        const float4 vz = make_float4(zz[c4], zz[c4 + 1], zz[c4 + 2], zz[c4 + 3]);
        const int ngrp = (N + 31) >> 5;   // 32-row groups

        for (int g = gwarp; g < ngrp; g += TOTAL_WARPS) {
            const int r0 = g * 32;
            const int fn = r0 + lane;
            const int f  = (fn < N) ? g_flag[fn] : 0;   // one coalesced load per warp
            const unsigned hits = __ballot_sync(FULL, f != 0);

            if (hits == 0 && r0 + 32 <= N) {
                const long base = (long)g * 512;        // float4 units (32 rows * 16)
#pragma unroll
                for (int j = 0; j < 16; j++)
                    out4[base + j * 32 + lane] = vz;
            } else {
                const int rend = min(r0 + 32, N);
                for (int r = r0; r < rend; r++) {
                    const int fr = __shfl_sync(FULL, f, r - r0);
                    float a0, a1;
                    if (fr) {
                        const float v0 = g_val[(long)r * CH + lane];
                        const float v1 = g_val[(long)r * CH + lane + 32];
                        a0 = (v0 - mm[lane])      * iv[lane];
                        a1 = (v1 - mm[lane + 32]) * iv[lane + 32];
                        a0 = (a0 >= 0.0f) ? a0 : 0.1f * a0;
                        a1 = (a1 >= 0.0f) ? a1 : 0.1f * a1;
                    } else {
                        a0 = zz[lane];
                        a1 = zz[lane + 32];
                    }
                    out[(long)r * CH + lane]      = a0;
                    out[(long)r * CH + lane + 32] = a1;
                }
            }
        }
    }
}

// ---------------- launch: ONE kernel ----------------
extern "C" void kernel_launch(void* const* d_in, const int* in_sizes, int n_in,
                              void* d_out, int out_size) {
    const float* q_pts = (const float*)d_in[0];
    const float* s_pts = (const float*)d_in[1];
    const int*   inds  = (const int*)  d_in[2];
    const float* x     = (const float*)d_in[3];
    const float* kp    = (const float*)d_in[4];
    const float* W     = (const float*)d_in[5];
    float* out = (float*)d_out;

    const int N = in_sizes[0] / 3;

    // non-stream attribute call: capture-safe, idempotent, no allocation
    cudaFuncSetAttribute(fused_kernel, cudaFuncAttributeMaxDynamicSharedMemorySize,
                         SMEM_BYTES);
    fused_kernel<<<NBLOCKS, NTHREADS, SMEM_BYTES>>>(q_pts, s_pts, inds, x, kp, W, out, N);
}

// round 17
// speedup vs baseline: 1.7314x; 1.1937x over previous
#include <cuda_runtime.h>
#include <math.h>

// Problem shape (fixed by dataset): N=100000, H=32, K=15, C_in=C_out=64
#define MAXN 100000
#define NB_H 32
#define KPTS 15
#define CH   64

#define NBLOCKS       592                // 148 SMs x 4 (co-resident via __launch_bounds__(256,4))
#define NTHREADS      256
#define TOTAL_THREADS (NBLOCKS * NTHREADS)
#define TOTAL_WARPS   (NBLOCKS * 8)

// Scratch (__device__ globals: allocation-free rule)
__device__ float4 g_pts4[MAXN];      // s_pts packed as float4 (w unused)
__device__ float  g_val[MAXN * CH];  // raw kpconv rows for flagged points
__device__ int    g_flag[MAXN];      // 1 if candidate row
__device__ float  g_sum[CH];
__device__ float  g_sumsq[CH];
// software grid barrier (self-resetting, safe across graph replays)
__device__ int          g_bar_count = 0;
__device__ volatile int g_bar_gen   = 0;

static __host__ __device__ __forceinline__ float kp_extent() {
    return (float)(0.1 * 1.2 / 2.5);
}

static __device__ __forceinline__ void grid_sync() {
    __threadfence();
    __syncthreads();
    if (threadIdx.x == 0) {
        const int gen = g_bar_gen;
        if (atomicAdd(&g_bar_count, 1) == NBLOCKS - 1) {
            g_bar_count = 0;
            __threadfence();
            g_bar_gen = gen + 1;
        } else {
            while (g_bar_gen == gen) { __nanosleep(32); }
        }
    }
    __syncthreads();
}

__global__ void __launch_bounds__(NTHREADS, 4) fused_kernel(
    const float* __restrict__ q_pts,
    const float* __restrict__ s_pts,
    const int*   __restrict__ inds,
    const float* __restrict__ x,
    const float* __restrict__ kp,
    const float* __restrict__ W,    // [K, C, C]
    float* __restrict__ out, int N)
{
    __shared__ float  sw[8][KPTS][CH];        // 30 KB, heavy-phase staging
    __shared__ float4 buf4[512];              // 8 KB constant pattern for TMA bulk stores
    __shared__ float  mm[CH], iv[CH], zz[CH]; // phase-C stats

    const int tid   = threadIdx.x;
    const int warp  = tid >> 5;
    const int lane  = tid & 31;
    const int gtid  = blockIdx.x * NTHREADS + tid;
    const int gwarp = blockIdx.x * 8 + warp;
    const unsigned FULL = 0xffffffffu;

    // conservative candidate threshold^2 (broadcast L1/L2 loads)
    float thr2;
    {
        float mx2 = 0.0f;
#pragma unroll
        for (int k = 0; k < KPTS; k++) {
            const float a = __ldg(kp + 3*k), b = __ldg(kp + 3*k + 1), c = __ldg(kp + 3*k + 2);
            mx2 = fmaxf(mx2, fmaf(a, a, fmaf(b, b, c * c)));
        }
        const float t = (kp_extent() + sqrtf(mx2)) * 1.0002f + 1e-6f;  // false positives ok
        thr2 = t * t;
    }

    // ---------------- Phase A: pack s_pts (vectorized float4), zero flags/sums ----------------
    {
        const float4* __restrict__ s4 = reinterpret_cast<const float4*>(s_pts);
        const int nq = N >> 2;   // groups of 4 points (100000 -> 25000, no remainder)
        for (int i = gtid; i < nq; i += TOTAL_THREADS) {
            const float4 a = __ldg(s4 + (long)i * 3);
            const float4 b = __ldg(s4 + (long)i * 3 + 1);
            const float4 c = __ldg(s4 + (long)i * 3 + 2);
            const int p = i << 2;
            g_pts4[p]     = make_float4(a.x, a.y, a.z, 0.0f);
            g_pts4[p + 1] = make_float4(a.w, b.x, b.y, 0.0f);
            g_pts4[p + 2] = make_float4(b.z, b.w, c.x, 0.0f);
            g_pts4[p + 3] = make_float4(c.y, c.z, c.w, 0.0f);
            *reinterpret_cast<int4*>(&g_flag[p]) = make_int4(0, 0, 0, 0);
        }
        for (int i = (nq << 2) + gtid; i < N; i += TOTAL_THREADS) {   // generic tail
            g_flag[i] = 0;
            g_pts4[i] = make_float4(__ldg(s_pts + 3*i), __ldg(s_pts + 3*i + 1),
                                    __ldg(s_pts + 3*i + 2), 0.0f);
        }
        if (blockIdx.x == 0 && tid < CH) { g_sum[tid] = 0.0f; g_sumsq[tid] = 0.0f; }
    }
    grid_sync();

    // ------- Phase B: detect. thread-per-quad (MLP=4), float4 gathers, flags only -------
    {
        const int nquad = N * (NB_H / 4);   // 800000 int4 quads
        for (int t = gtid; t < nquad; t += TOTAL_THREADS) {
            const int n = t >> 3;           // 8 quads per point; q loads broadcast in-warp
            const float qx = __ldg(q_pts + 3*n);
            const float qy = __ldg(q_pts + 3*n + 1);
            const float qz = __ldg(q_pts + 3*n + 2);

            const int4 iv4 = __ldg(reinterpret_cast<const int4*>(inds) + t);

            // dataset guarantees idx in [0, N): no bounds checks (heavy path re-verifies)
            const float4 p0 = __ldg(&g_pts4[iv4.x]);
            const float4 p1 = __ldg(&g_pts4[iv4.y]);
            const float4 p2 = __ldg(&g_pts4[iv4.z]);
            const float4 p3 = __ldg(&g_pts4[iv4.w]);

            float dx, dy, dz;
            bool any = false;
            dx = p0.x - qx; dy = p0.y - qy; dz = p0.z - qz;
            any |= (fmaf(dx, dx, fmaf(dy, dy, dz * dz)) < thr2);
            dx = p1.x - qx; dy = p1.y - qy; dz = p1.z - qz;
            any |= (fmaf(dx, dx, fmaf(dy, dy, dz * dz)) < thr2);
            dx = p2.x - qx; dy = p2.y - qy; dz = p2.z - qz;
            any |= (fmaf(dx, dx, fmaf(dy, dy, dz * dz)) < thr2);
            dx = p3.x - qx; dy = p3.y - qy; dz = p3.z - qz;
            any |= (fmaf(dx, dx, fmaf(dy, dy, dz * dz)) < thr2);

            if (any) g_flag[n] = 1;         // racy same-value store: benign
        }
    }
    grid_sync();

    // ---------------- Phase B2: heavy. ballot-scan flags, exact KPConv per hit ----------------
    {
        const float EXT  = kp_extent();
        const float EXT2 = EXT * EXT;
        const float INVE = 1.0f / EXT;

        const int ngrp = (N + 31) >> 5;
        for (int g = gwarp; g < ngrp; g += TOTAL_WARPS) {
            const int fn = g * 32 + lane;
            const int f = (fn < N) ? g_flag[fn] : 0;
            unsigned hits = __ballot_sync(FULL, f != 0);

            while (hits) {
                const int bit = __ffs(hits) - 1;
                hits &= (hits - 1);
                const int n = g * 32 + bit;

                const float qx = __ldg(q_pts + 3*n);
                const float qy = __ldg(q_pts + 3*n + 1);
                const float qz = __ldg(q_pts + 3*n + 2);

                const int idx = __ldg(inds + (long)n * NB_H + lane);
                const bool valid = ((unsigned)idx < (unsigned)N);
                float nx = 1e9f, ny = 1e9f, nz = 1e9f;
                if (valid) {
                    const float4 p = __ldg(&g_pts4[idx]);
                    nx = p.x - qx; ny = p.y - qy; nz = p.z - qz;
                }
                const float r2 = fmaf(nx, nx, fmaf(ny, ny, nz * nz));
                unsigned mask = __ballot_sync(FULL, valid && (r2 < thr2));

                float acc0[KPTS], acc1[KPTS];
#pragma unroll
                for (int k = 0; k < KPTS; k++) { acc0[k] = 0.0f; acc1[k] = 0.0f; }

                unsigned m = mask;
                while (m) {
                    const int hs = __ffs(m) - 1;
                    m &= (m - 1);
                    const int   sidx = __shfl_sync(FULL, idx, hs);
                    const float bx = __shfl_sync(FULL, nx, hs);
                    const float by = __shfl_sync(FULL, ny, hs);
                    const float bz = __shfl_sync(FULL, nz, hs);
                    const float xv0 = __ldg(x + (long)sidx * CH + lane);
                    const float xv1 = __ldg(x + (long)sidx * CH + lane + 32);
#pragma unroll
                    for (int k = 0; k < KPTS; k++) {
                        const float dx = bx - __ldg(kp + 3*k);
                        const float dy = by - __ldg(kp + 3*k + 1);
                        const float dz = bz - __ldg(kp + 3*k + 2);
                        const float d2 = fmaf(dx, dx, fmaf(dy, dy, dz * dz));
                        if (d2 < EXT2) {
                            const float w = fmaxf(1.0f - sqrtf(d2) * INVE, 0.0f);
                            acc0[k] = fmaf(w, xv0, acc0[k]);
                            acc1[k] = fmaf(w, xv1, acc1[k]);
                        }
                    }
                }

                unsigned kmask = 0;
#pragma unroll
                for (int k = 0; k < KPTS; k++) {
                    sw[warp][k][lane]      = acc0[k];
                    sw[warp][k][lane + 32] = acc1[k];
                    if (__ballot_sync(FULL, (acc0[k] != 0.0f) || (acc1[k] != 0.0f)))
                        kmask |= (1u << k);
                }
                __syncwarp();

                float o0 = 0.0f, o1 = 0.0f;
                for (int k = 0; k < KPTS; k++) {
                    if (!(kmask & (1u << k))) continue;
                    const float* Wk = W + (long)k * CH * CH;
#pragma unroll 8
                    for (int c = 0; c < CH; c++) {
                        const float wv = sw[warp][k][c];
                        o0 = fmaf(wv, __ldg(Wk + c * CH + lane),      o0);
                        o1 = fmaf(wv, __ldg(Wk + c * CH + lane + 32), o1);
                    }
                }
                __syncwarp();

                g_val[(long)n * CH + lane]      = o0;
                g_val[(long)n * CH + lane + 32] = o1;
                atomicAdd(&g_sum[lane],        o0);
                atomicAdd(&g_sum[lane + 32],   o1);
                atomicAdd(&g_sumsq[lane],      o0 * o0);
                atomicAdd(&g_sumsq[lane + 32], o1 * o1);
            }
        }
    }
    grid_sync();

    // ---------------- Phase C: finalize stats; TMA bulk-store the constant everywhere ----------------
    if (tid < CH) {
        const float invN = 1.0f / (float)N;
        const float mean = g_sum[tid] * invN;
        const float var  = fmaxf(g_sumsq[tid] * invN - mean * mean, 0.0f);
        const float inv  = rsqrtf(var + 1e-5f);
        const float z    = (0.0f - mean) * inv;
        mm[tid] = mean;
        iv[tid] = inv;
        zz[tid] = (z >= 0.0f) ? z : 0.1f * z;
    }
    __syncthreads();

    {
        // fill 8 KB smem with 32 rows of the normalized-zero constant
#pragma unroll
        for (int j = tid; j < 512; j += NTHREADS) {
            const int c4 = (j & 15) * 4;
            buf4[j] = make_float4(zz[c4], zz[c4 + 1], zz[c4 + 2], zz[c4 + 3]);
        }
        __syncthreads();

        if (tid == 0) {
            asm volatile("fence.proxy.async.shared::cta;" ::: "memory");
            const unsigned saddr = (unsigned)__cvta_generic_to_shared(buf4);
            const long B = (long)N * CH * 4;          // output bytes
            const long nfull = B >> 13;               // 8 KB chunks
            char* const ob = reinterpret_cast<char*>(out);
            for (long k = blockIdx.x; k < nfull; k += NBLOCKS) {
                asm volatile("cp.async.bulk.global.shared::cta.bulk_group [%0], [%1], %2;"
                             :: "l"(ob + (k << 13)), "r"(saddr), "r"(8192u) : "memory");
            }
            const unsigned tail = (unsigned)(B & 8191);
            if (tail && blockIdx.x == 0) {            // tail is a multiple of 256 (row size)
                asm volatile("cp.async.bulk.global.shared::cta.bulk_group [%0], [%1], %2;"
                             :: "l"(ob + (nfull << 13)), "r"(saddr), "r"(tail) : "memory");
            }
            asm volatile("cp.async.bulk.commit_group;" ::: "memory");
            asm volatile("cp.async.bulk.wait_group 0;" ::: "memory");
        }
    }
    grid_sync();   // all constant stores complete chip-wide before fixup overwrites

    // ---------------- Phase D: fixup the rare active rows with exact normalized values ----------------
    {
        const int ngrp = (N + 31) >> 5;
        for (int g = gwarp; g < ngrp; g += TOTAL_WARPS) {
            const int fn = g * 32 + lane;
            const int f = (fn < N) ? g_flag[fn] : 0;
            unsigned hits = __ballot_sync(FULL, f != 0);
            while (hits) {
                const int bit = __ffs(hits) - 1;
                hits &= (hits - 1);
                const int n = g * 32 + bit;
                const float v0 = g_val[(long)n * CH + lane];
                const float v1 = g_val[(long)n * CH + lane + 32];
                float a0 = (v0 - mm[lane])      * iv[lane];
                float a1 = (v1 - mm[lane + 32]) * iv[lane + 32];
                a0 = (a0 >= 0.0f) ? a0 : 0.1f * a0;
                a1 = (a1 >= 0.0f) ? a1 : 0.1f * a1;
                out[(long)n * CH + lane]      = a0;
                out[(long)n * CH + lane + 32] = a1;
            }
        }
    }
}

// ---------------- launch: ONE kernel ----------------
extern "C" void kernel_launch(void* const* d_in, const int* in_sizes, int n_in,
                              void* d_out, int out_size) {
    const float* q_pts = (const float*)d_in[0];
    const float* s_pts = (const float*)d_in[1];
    const int*   inds  = (const int*)  d_in[2];
    const float* x     = (const float*)d_in[3];
    const float* kp    = (const float*)d_in[4];
    const float* W     = (const float*)d_in[5];
    float* out = (float*)d_out;

    const int N = in_sizes[0] / 3;

    fused_kernel<<<NBLOCKS, NTHREADS>>>(q_pts, s_pts, inds, x, kp, W, out, N);
}